// round 2
// baseline (speedup 1.0000x reference)
#include <cuda_runtime.h>
#include <math.h>

// fl(sqrt(2)) and fl(1.5/sqrt(2)) exactly as numpy computes them (double -> float32).
// KODD = fp32 product, used for the sqrt2 / odd-exponent branch:
//   reference: pow(sqrt2f, e) * APPROX  ==  2^((e-1)/2) * (sqrt2f * APPROXf)  (within ~2 ulp)
__device__ __forceinline__ float quant_one(float x, float z, float c, float L,
                                           float s, float ls, float low)
{
    const float SQRT2F  = (float)1.4142135623730951;
    const float APPROXF = (float)1.0606601717798212;   // 1.5/sqrt(2) rounded to fp32
    const float KODD    = SQRT2F * APPROXF;            // constant-folded fp32 product

    float ax = fabsf(x);
    // log2(|x|/s) = log2|x| - log2(s); reference's +1e-32 only matters at x==0,
    // where log2f(0) = -inf drives the same zero-flag path (sign(0)=0 anyway).
    float xl = log2f(ax) - ls;
    bool  rt2 = (c != 2.0f);                 // code_map is exactly 2.0f or sqrt2f
    if (rt2) xl += xl;                       // log base sqrt2 = 2 * log2
    float xi = rintf(xl);                    // round-half-even == jnp.round
    float c1 = fmaxf(xi - z, low);           // clamp(min=lower)
    float xc = fminf(c1 - L, -1.0f);         // clamp(max=-1)
    float e  = xc + L + z;                   // integer in [-7, 9] on all live paths

    int ei = (int)e;                         // exact for integral e; dead paths don't care
    float q;
    if (rt2) {
        int h = ei >> 1;                     // floor(e/2), arithmetic shift
        q = __int_as_float((h + 127) << 23); // 2^h  (exact)
        if (ei & 1) q *= KODD;               // odd e: 2^h * sqrt2 * approx_factor
    } else {
        q = __int_as_float((ei + 127) << 23);// 2^e  (exact, matches pow(2,e))
    }
    if (c1 <= low) q = 0.0f;                 // underflow -> exact 0
    return q * copysignf(s, x);              // q * sign(x) * scale (x==0 -> q==0)
}

// One fused kernel. Each thread processes 2 consecutive float4s (8 elems, same row:
// 2752 float4/row -> 1376 pairs/row, divides exactly). 8 front-batched streaming
// LDG.128s maximize memory-level parallelism; row params are broadcast L2 hits.
__global__ void __launch_bounds__(256)
quant_kernel(const float4* __restrict__ X,
             const float4* __restrict__ Z,
             const float4* __restrict__ C,
             const float4* __restrict__ L,
             const float*  __restrict__ scale,
             const float*  __restrict__ asym,
             float4* __restrict__ O,
             int npair)
{
    const int PAIRS_PER_ROW = (11008 / 4) / 2;   // 1376 (compile-time divisor -> mulhi)
    int t = blockIdx.x * blockDim.x + threadIdx.x;
    if (t >= npair) return;
    int row = t / PAIRS_PER_ROW;
    int i0  = t * 2;
    int i1  = i0 + 1;

    // Front-batch all global loads (MLP). Streaming: zero reuse, evict-first.
    float4 x0 = __ldcs(X + i0), x1 = __ldcs(X + i1);
    float4 z0 = __ldcs(Z + i0), z1 = __ldcs(Z + i1);
    float4 c0 = __ldcs(C + i0), c1 = __ldcs(C + i1);
    float4 l0 = __ldcs(L + i0), l1 = __ldcs(L + i1);
    float  s  = __ldg(scale + row);              // broadcast, L2-resident (16KB)
    float  a  = __ldg(asym  + row);

    float ls  = log2f(s);                        // once per 8 elements
    float low = fmaf(a, -0.5f, -1.0f);           // -1 - asym/2

    float4 o0, o1;
    o0.x = quant_one(x0.x, z0.x, c0.x, l0.x, s, ls, low);
    o0.y = quant_one(x0.y, z0.y, c0.y, l0.y, s, ls, low);
    o0.z = quant_one(x0.z, z0.z, c0.z, l0.z, s, ls, low);
    o0.w = quant_one(x0.w, z0.w, c0.w, l0.w, s, ls, low);
    o1.x = quant_one(x1.x, z1.x, c1.x, l1.x, s, ls, low);
    o1.y = quant_one(x1.y, z1.y, c1.y, l1.y, s, ls, low);
    o1.z = quant_one(x1.z, z1.z, c1.z, l1.z, s, ls, low);
    o1.w = quant_one(x1.w, z1.w, c1.w, l1.w, s, ls, low);
    __stcs(O + i0, o0);
    __stcs(O + i1, o1);
}

extern "C" void kernel_launch(void* const* d_in, const int* in_sizes, int n_in,
                              void* d_out, int out_size)
{
    // metadata order: x, scale, zero, code_map, level_map, asym_map
    const float* x     = (const float*)d_in[0];
    const float* scale = (const float*)d_in[1];
    const float* zero  = (const float*)d_in[2];
    const float* code  = (const float*)d_in[3];
    const float* level = (const float*)d_in[4];
    const float* asym  = (const float*)d_in[5];

    int npair  = out_size / 8;                   // total elems / 8 (11008 % 8 == 0)
    int blocks = (npair + 255) / 256;

    quant_kernel<<<blocks, 256>>>((const float4*)x, (const float4*)zero,
                                  (const float4*)code, (const float4*)level,
                                  scale, asym, (float4*)d_out, npair);
}

// round 3
// speedup vs baseline: 1.0310x; 1.0310x over previous
#include <cuda_runtime.h>
#include <math.h>

// fl(sqrt(2)) and fl(1.5/sqrt(2)) exactly as numpy computes them (double -> float32).
// KODD = fp32 product, used for the sqrt2 / odd-exponent branch:
//   reference: pow(sqrt2f, e) * APPROX  ==  2^((e-1)/2) * (sqrt2f * APPROXf)  (within ~2 ulp)
__device__ __forceinline__ float quant_one(float x, float z, float c, float L,
                                           float s, float ls, float low)
{
    const float SQRT2F  = (float)1.4142135623730951;
    const float APPROXF = (float)1.0606601717798212;   // 1.5/sqrt(2) rounded to fp32
    const float KODD    = SQRT2F * APPROXF;            // constant-folded fp32 product

    float ax = fabsf(x);
    // log2(|x|/s) = log2|x| - log2(s); reference's +1e-32 only matters at x==0,
    // where log2f(0) = -inf drives the same zero-flag path (sign(0)=0 anyway).
    float xl = log2f(ax) - ls;
    bool  rt2 = (c != 2.0f);                 // code_map is exactly 2.0f or sqrt2f
    if (rt2) xl += xl;                       // log base sqrt2 = 2 * log2
    float xi = rintf(xl);                    // round-half-even == jnp.round
    float c1 = fmaxf(xi - z, low);           // clamp(min=lower)
    float xc = fminf(c1 - L, -1.0f);         // clamp(max=-1)
    float e  = xc + L + z;                   // integer in [-7, 9] on all live paths

    int ei = (int)e;                         // exact for integral e; dead paths don't care
    float q;
    if (rt2) {
        int h = ei >> 1;                     // floor(e/2), arithmetic shift
        q = __int_as_float((h + 127) << 23); // 2^h  (exact)
        if (ei & 1) q *= KODD;               // odd e: 2^h * sqrt2 * approx_factor
    } else {
        q = __int_as_float((ei + 127) << 23);// 2^e  (exact, matches pow(2,e))
    }
    if (c1 <= low) q = 0.0f;                 // underflow -> exact 0
    return q * copysignf(s, x);              // q * sign(x) * scale (x==0 -> q==0)
}

// Single fused kernel, R1 memory shape: 1 float4 per thread, default cache ops.
// Row params (scale, asym) are tiny (32KB) broadcast L2-resident reads; log2f(s)
// computed per thread (fma pipe has 70% headroom).
__global__ void __launch_bounds__(256)
quant_kernel(const float4* __restrict__ X,
             const float4* __restrict__ Z,
             const float4* __restrict__ C,
             const float4* __restrict__ L,
             const float*  __restrict__ scale,
             const float*  __restrict__ asym,
             float4* __restrict__ O,
             int nvec)
{
    const int COLSV = 11008 / 4;             // 2752 float4 per row (compile-time divisor)
    int idx = blockIdx.x * blockDim.x + threadIdx.x;
    if (idx >= nvec) return;
    int row = idx / COLSV;

    // Front-batch the 4 wide loads (MLP_p1=4, same as R1) + 2 broadcast scalars.
    float4 x = X[idx];
    float4 z = Z[idx];
    float4 c = C[idx];
    float4 l = L[idx];
    float  s = __ldg(scale + row);
    float  a = __ldg(asym  + row);

    float ls  = log2f(s);
    float low = fmaf(a, -0.5f, -1.0f);       // -1 - asym/2

    float4 o;
    o.x = quant_one(x.x, z.x, c.x, l.x, s, ls, low);
    o.y = quant_one(x.y, z.y, c.y, l.y, s, ls, low);
    o.z = quant_one(x.z, z.z, c.z, l.z, s, ls, low);
    o.w = quant_one(x.w, z.w, c.w, l.w, s, ls, low);
    O[idx] = o;
}

extern "C" void kernel_launch(void* const* d_in, const int* in_sizes, int n_in,
                              void* d_out, int out_size)
{
    // metadata order: x, scale, zero, code_map, level_map, asym_map
    const float* x     = (const float*)d_in[0];
    const float* scale = (const float*)d_in[1];
    const float* zero  = (const float*)d_in[2];
    const float* code  = (const float*)d_in[3];
    const float* level = (const float*)d_in[4];
    const float* asym  = (const float*)d_in[5];

    int nvec   = out_size / 4;               // total elems / 4 (COLS divisible by 4)
    int blocks = (nvec + 255) / 256;

    quant_kernel<<<blocks, 256>>>((const float4*)x, (const float4*)zero,
                                  (const float4*)code, (const float4*)level,
                                  scale, asym, (float4*)d_out, nvec);
}